// round 1
// baseline (speedup 1.0000x reference)
#include <cuda_runtime.h>

#define NB 8
#define NI 64
#define NO 64
#define NN 8192
#define NK 16
#define ND 3
#define NH1 16
#define NH2 32
#define TN 8                 // n values per CTA
#define ROWS 128             // TN * NK
#define NTHREADS 128
#define BON (NB*NO*NN)       // 4194304
#define SPN (NB*ND*NN)       // 196608

// shared memory layout (floats)
//  sW   : NI*NO   = 4096
//  sX   : NI*ROWS = 8192
//  sH2  : NH2*ROWS= 4096
//  sW3  : NH2*NO  = 2048
//  sW1  : 48, sb1:16, sW2:512, sb2:32, sb3:64, sBias:64, sOut:512
#define SMEM_FLOATS (4096+8192+4096+2048+48+16+512+32+64+64+512)
#define SMEM_BYTES (SMEM_FLOATS*4)

__global__ void __launch_bounds__(NTHREADS, 2)
pccn_kernel(const float* __restrict__ input, const float* __restrict__ points,
            const float* __restrict__ support, const float* __restrict__ weight,
            const float* __restrict__ bias, const float* __restrict__ W1,
            const float* __restrict__ b1, const float* __restrict__ W2,
            const float* __restrict__ b2, const float* __restrict__ W3,
            const float* __restrict__ b3, float* __restrict__ out, int copy_sp)
{
    extern __shared__ float sm[];
    float* sW    = sm;            // [i][o]
    float* sX    = sW  + 4096;    // [i][row]
    float* sH2   = sX  + 8192;    // [j][row]
    float* sW3   = sH2 + 4096;    // [j][o]
    float* sW1   = sW3 + 2048;    // [d][a] 3x16
    float* sb1   = sW1 + 48;
    float* sW2   = sb1 + 16;      // [a][j] 16x32
    float* sb2   = sW2 + 512;
    float* sb3   = sb2 + 32;
    float* sBias = sb3 + 64;
    float* sOut  = sBias + 64;    // [n_local][o] 8x64

    const int tid = threadIdx.x;
    const int blk = blockIdx.x;
    const int b   = blk >> 10;          // NN/TN = 1024 tiles per batch
    const int n0  = (blk & 1023) * TN;

    // ---- cooperative loads to smem ----
    for (int idx = tid; idx < (NI*NO)/4; idx += NTHREADS)
        ((float4*)sW)[idx] = ((const float4*)weight)[idx];

    for (int idx = tid; idx < (NI*ROWS)/4; idx += NTHREADS) {
        int i = idx >> 5, c = idx & 31;   // 32 float4 per i-row
        ((float4*)(sX + i*ROWS))[c] =
            *(const float4*)(input + (((size_t)b*NI + i)*NN + n0)*NK + c*4);
    }
    for (int idx = tid; idx < (NH2*NO)/4; idx += NTHREADS)
        ((float4*)sW3)[idx] = ((const float4*)W3)[idx];

    if (tid < 48) sW1[tid] = W1[tid];
    if (tid < 16) sb1[tid] = b1[tid];
    for (int idx = tid; idx < NH1*NH2; idx += NTHREADS) sW2[idx] = W2[idx];
    if (tid < 32) sb2[tid] = b2[tid];
    if (tid < 64) sb3[tid] = b3[tid];
    if (tid < 64) sBias[tid] = bias[tid];
    for (int idx = tid; idx < TN*NO; idx += NTHREADS) sOut[idx] = 0.0f;

    // ---- per-row (b,n,k) relative coords + normalization ----
    const int n_loc = tid >> 4;           // row = n_loc*16 + k  (row == tid)
    const int k     = tid & 15;
    const int n     = n0 + n_loc;

    float p0 = points[(((size_t)b*ND + 0)*NN + n)*NK + k] - support[((size_t)b*ND + 0)*NN + n];
    float p1 = points[(((size_t)b*ND + 1)*NN + n)*NK + k] - support[((size_t)b*ND + 1)*NN + n];
    float p2 = points[(((size_t)b*ND + 2)*NN + n)*NK + k] - support[((size_t)b*ND + 2)*NN + n];

    float sq = p0*p0 + p1*p1 + p2*p2;
    float m = sq;
#pragma unroll
    for (int off = 8; off > 0; off >>= 1)
        m = fmaxf(m, __shfl_xor_sync(0xffffffffu, m, off));  // max over the 16 k's
    float maxi = sqrtf(m);
    maxi += (maxi == 0.0f) ? 1.0f : 0.0f;
    float inv = 1.0f / maxi;
    float x0 = p0*inv, x1 = p1*inv, x2 = p2*inv;

    __syncthreads();   // smem weights + sX ready

    // ---- tiny MLP to h2, store transposed [j][row] ----
    float h1[NH1];
#pragma unroll
    for (int a = 0; a < NH1; a++) {
        float v = sb1[a] + x0*sW1[a] + x1*sW1[16 + a] + x2*sW1[32 + a];
        h1[a] = fmaxf(v, 0.0f);
    }
    float h2[NH2];
#pragma unroll
    for (int j = 0; j < NH2; j++) h2[j] = sb2[j];
#pragma unroll
    for (int a = 0; a < NH1; a++) {
        float v = h1[a];
#pragma unroll
        for (int j = 0; j < NH2; j++) h2[j] += v * sW2[a*NH2 + j];
    }
#pragma unroll
    for (int j = 0; j < NH2; j++)
        sH2[j*ROWS + tid] = fmaxf(h2[j], 0.0f);

    __syncthreads();

    // ---- two register-tiled GEMMs over the SAME 8x8 (row,o) tile ----
    const int tr = tid >> 3, tc = tid & 7;
    const int row0 = tr * 8, o0 = tc * 8;

    // mat = h2 @ W3 + b3   (K-dim 32)
    float macc[8][8];
#pragma unroll
    for (int rr = 0; rr < 8; rr++)
#pragma unroll
        for (int oo = 0; oo < 8; oo++) macc[rr][oo] = sb3[o0 + oo];

#pragma unroll 8
    for (int j = 0; j < NH2; j++) {
        float4 xa = *(const float4*)(sH2 + j*ROWS + row0);
        float4 xb = *(const float4*)(sH2 + j*ROWS + row0 + 4);
        float4 wa = *(const float4*)(sW3 + j*NO + o0);
        float4 wb = *(const float4*)(sW3 + j*NO + o0 + 4);
        float xr[8] = {xa.x,xa.y,xa.z,xa.w,xb.x,xb.y,xb.z,xb.w};
        float wr[8] = {wa.x,wa.y,wa.z,wa.w,wb.x,wb.y,wb.z,wb.w};
#pragma unroll
        for (int rr = 0; rr < 8; rr++)
#pragma unroll
            for (int oo = 0; oo < 8; oo++) macc[rr][oo] += xr[rr]*wr[oo];
    }

    // F = X^T @ weight   (K-dim 64)
    float facc[8][8];
#pragma unroll
    for (int rr = 0; rr < 8; rr++)
#pragma unroll
        for (int oo = 0; oo < 8; oo++) facc[rr][oo] = 0.0f;

#pragma unroll 4
    for (int i = 0; i < NI; i++) {
        float4 xa = *(const float4*)(sX + i*ROWS + row0);
        float4 xb = *(const float4*)(sX + i*ROWS + row0 + 4);
        float4 wa = *(const float4*)(sW  + i*NO + o0);
        float4 wb = *(const float4*)(sW  + i*NO + o0 + 4);
        float xr[8] = {xa.x,xa.y,xa.z,xa.w,xb.x,xb.y,xb.z,xb.w};
        float wr[8] = {wa.x,wa.y,wa.z,wa.w,wb.x,wb.y,wb.z,wb.w};
#pragma unroll
        for (int rr = 0; rr < 8; rr++)
#pragma unroll
            for (int oo = 0; oo < 8; oo++) facc[rr][oo] += xr[rr]*wr[oo];
    }

    // ---- combine: out[n,o] = sum_k F*mat (k-reduction over rows) ----
    float partial[8];
#pragma unroll
    for (int oo = 0; oo < 8; oo++) partial[oo] = 0.0f;
#pragma unroll
    for (int rr = 0; rr < 8; rr++)
#pragma unroll
        for (int oo = 0; oo < 8; oo++) partial[oo] += facc[rr][oo]*macc[rr][oo];

    const int my_nl = tr >> 1;   // rows row0..row0+7 all belong to n_local = tr/2
#pragma unroll
    for (int oo = 0; oo < 8; oo++)
        atomicAdd(&sOut[my_nl*NO + o0 + oo], partial[oo]);

    __syncthreads();

    // ---- epilogue: out layout (B, O, N), + bias ----
    for (int idx = tid; idx < TN*NO; idx += NTHREADS) {
        int o = idx >> 3, nl = idx & 7;
        out[((size_t)b*NO + o)*NN + n0 + nl] = sOut[nl*NO + o] + sBias[o];
    }

    // ---- second tuple element: support_points passthrough ----
    if (copy_sp) {
        for (int idx = blk*NTHREADS + tid; idx < SPN; idx += gridDim.x*NTHREADS)
            out[BON + idx] = support[idx];
    }
}

extern "C" void kernel_launch(void* const* d_in, const int* in_sizes, int n_in,
                              void* d_out, int out_size) {
    const float* input   = (const float*)d_in[0];
    const float* points  = (const float*)d_in[1];
    const float* support = (const float*)d_in[2];
    const float* weight  = (const float*)d_in[3];
    const float* bias    = (const float*)d_in[4];
    const float* W1      = (const float*)d_in[5];
    const float* b1      = (const float*)d_in[6];
    const float* W2      = (const float*)d_in[7];
    const float* b2      = (const float*)d_in[8];
    const float* W3      = (const float*)d_in[9];
    const float* b3      = (const float*)d_in[10];

    static int inited = 0;
    if (!inited) {
        cudaFuncSetAttribute(pccn_kernel,
                             cudaFuncAttributeMaxDynamicSharedMemorySize,
                             SMEM_BYTES);
        inited = 1;
    }
    int copy_sp = (out_size > BON) ? 1 : 0;
    pccn_kernel<<<NB*(NN/TN), NTHREADS, SMEM_BYTES>>>(
        input, points, support, weight, bias, W1, b1, W2, b2, W3, b3,
        (float*)d_out, copy_sp);
}

// round 2
// speedup vs baseline: 1.0672x; 1.0672x over previous
#include <cuda_runtime.h>

#define NB 8
#define NI 64
#define NO 64
#define NN 8192
#define NK 16
#define ND 3
#define NH1 16
#define NH2 32
#define TN 8                 // n values per CTA
#define ROWS 128             // TN * NK
#define NTHREADS 128
#define BON (NB*NO*NN)       // 4194304
#define SPN (NB*ND*NN)       // 196608

// shared memory layout (floats)
#define SMEM_FLOATS (4096+8192+4096+2048+48+16+512+32+64+64+512)
#define SMEM_BYTES (SMEM_FLOATS*4)

typedef unsigned long long u64;

__device__ __forceinline__ u64 pack2(float x, float y) {
    u64 r; asm("mov.b64 %0,{%1,%2};" : "=l"(r) : "f"(x), "f"(y)); return r;
}
__device__ __forceinline__ u64 fma2(u64 a, u64 b, u64 c) {
    u64 d; asm("fma.rn.f32x2 %0,%1,%2,%3;" : "=l"(d) : "l"(a), "l"(b), "l"(c)); return d;
}
__device__ __forceinline__ float2 unpack2(u64 v) {
    float2 f; asm("mov.b64 {%0,%1},%2;" : "=f"(f.x), "=f"(f.y) : "l"(v)); return f;
}

__global__ void __launch_bounds__(NTHREADS, 2)
pccn_kernel(const float* __restrict__ input, const float* __restrict__ points,
            const float* __restrict__ support, const float* __restrict__ weight,
            const float* __restrict__ bias, const float* __restrict__ W1,
            const float* __restrict__ b1, const float* __restrict__ W2,
            const float* __restrict__ b2, const float* __restrict__ W3,
            const float* __restrict__ b3, float* __restrict__ out, int copy_sp)
{
    extern __shared__ float sm[];
    float* sW    = sm;            // [i][o]
    float* sX    = sW  + 4096;    // [i][row]
    float* sH2   = sX  + 8192;    // [j][row]
    float* sW3   = sH2 + 4096;    // [j][o]
    float* sW1   = sW3 + 2048;    // [d][a] 3x16
    float* sb1   = sW1 + 48;
    float* sW2   = sb1 + 16;      // [a][j] 16x32
    float* sb2   = sW2 + 512;
    float* sb3   = sb2 + 32;
    float* sBias = sb3 + 64;
    float* sOut  = sBias + 64;    // [n_local][o] 8x64

    const int tid = threadIdx.x;
    const int blk = blockIdx.x;
    const int b   = blk >> 10;          // NN/TN = 1024 tiles per batch
    const int n0  = (blk & 1023) * TN;

    // ---- cooperative loads to smem ----
    for (int idx = tid; idx < (NI*NO)/4; idx += NTHREADS)
        ((float4*)sW)[idx] = ((const float4*)weight)[idx];

    for (int idx = tid; idx < (NI*ROWS)/4; idx += NTHREADS) {
        int i = idx >> 5, c = idx & 31;   // 32 float4 per i-row
        ((float4*)(sX + i*ROWS))[c] =
            *(const float4*)(input + (((size_t)b*NI + i)*NN + n0)*NK + c*4);
    }
    for (int idx = tid; idx < (NH2*NO)/4; idx += NTHREADS)
        ((float4*)sW3)[idx] = ((const float4*)W3)[idx];

    if (tid < 48) sW1[tid] = W1[tid];
    if (tid < 16) sb1[tid] = b1[tid];
    for (int idx = tid; idx < NH1*NH2; idx += NTHREADS) sW2[idx] = W2[idx];
    if (tid < 32) sb2[tid] = b2[tid];
    if (tid < 64) sb3[tid] = b3[tid];
    if (tid < 64) sBias[tid] = bias[tid];
    for (int idx = tid; idx < TN*NO; idx += NTHREADS) sOut[idx] = 0.0f;

    // ---- per-row (b,n,k) relative coords + normalization ----
    const int k = tid & 15;
    const int n = n0 + (tid >> 4);

    float p0 = points[(((size_t)b*ND + 0)*NN + n)*NK + k] - support[((size_t)b*ND + 0)*NN + n];
    float p1 = points[(((size_t)b*ND + 1)*NN + n)*NK + k] - support[((size_t)b*ND + 1)*NN + n];
    float p2 = points[(((size_t)b*ND + 2)*NN + n)*NK + k] - support[((size_t)b*ND + 2)*NN + n];

    float sq = p0*p0 + p1*p1 + p2*p2;
    float m = sq;
#pragma unroll
    for (int off = 8; off > 0; off >>= 1)
        m = fmaxf(m, __shfl_xor_sync(0xffffffffu, m, off));  // max over the 16 k's
    float maxi = sqrtf(m);
    maxi += (maxi == 0.0f) ? 1.0f : 0.0f;
    float inv = 1.0f / maxi;
    float x0 = p0*inv, x1 = p1*inv, x2 = p2*inv;

    __syncthreads();   // smem weights + sX ready

    // ---- tiny MLP to h2 (packed f32x2 on the 16->32 layer) ----
    float h1[NH1];
#pragma unroll
    for (int a = 0; a < NH1; a++) {
        float v = sb1[a] + x0*sW1[a] + x1*sW1[16 + a] + x2*sW1[32 + a];
        h1[a] = fmaxf(v, 0.0f);
    }
    u64 h2p[NH2/2];
#pragma unroll
    for (int jp = 0; jp < NH2/2; jp++) h2p[jp] = ((const u64*)sb2)[jp];
#pragma unroll
    for (int a = 0; a < NH1; a++) {
        u64 xd = pack2(h1[a], h1[a]);
        const u64* wrow = (const u64*)(sW2 + a*NH2);
#pragma unroll
        for (int jp = 0; jp < NH2/2; jp++) h2p[jp] = fma2(xd, wrow[jp], h2p[jp]);
    }
#pragma unroll
    for (int jp = 0; jp < NH2/2; jp++) {
        float2 v = unpack2(h2p[jp]);
        sH2[(2*jp+0)*ROWS + tid] = fmaxf(v.x, 0.0f);
        sH2[(2*jp+1)*ROWS + tid] = fmaxf(v.y, 0.0f);
    }

    __syncthreads();

    // ---- two register-tiled GEMMs over the SAME 8x8 (row,o) tile ----
    // accumulators packed along o: [rr][op] holds (o0+2op, o0+2op+1)
    const int tr = tid >> 3, tc = tid & 7;
    const int row0 = tr * 8, o0 = tc * 8;

    // mat = h2 @ W3 + b3   (K-dim 32)
    u64 macc[8][4];
    {
        const u64* bp = (const u64*)(sb3 + o0);
        u64 b0 = bp[0], b1p = bp[1], b2p = bp[2], b3p = bp[3];
#pragma unroll
        for (int rr = 0; rr < 8; rr++) {
            macc[rr][0] = b0; macc[rr][1] = b1p; macc[rr][2] = b2p; macc[rr][3] = b3p;
        }
    }
#pragma unroll 4
    for (int j = 0; j < NH2; j++) {
        const float4 xa = *(const float4*)(sH2 + j*ROWS + row0);
        const float4 xb = *(const float4*)(sH2 + j*ROWS + row0 + 4);
        u64 xd[8];
        xd[0]=pack2(xa.x,xa.x); xd[1]=pack2(xa.y,xa.y); xd[2]=pack2(xa.z,xa.z); xd[3]=pack2(xa.w,xa.w);
        xd[4]=pack2(xb.x,xb.x); xd[5]=pack2(xb.y,xb.y); xd[6]=pack2(xb.z,xb.z); xd[7]=pack2(xb.w,xb.w);
        const u64* wp = (const u64*)(sW3 + j*NO + o0);
        u64 w0 = wp[0], w1 = wp[1], w2 = wp[2], w3 = wp[3];
#pragma unroll
        for (int rr = 0; rr < 8; rr++) {
            macc[rr][0] = fma2(xd[rr], w0, macc[rr][0]);
            macc[rr][1] = fma2(xd[rr], w1, macc[rr][1]);
            macc[rr][2] = fma2(xd[rr], w2, macc[rr][2]);
            macc[rr][3] = fma2(xd[rr], w3, macc[rr][3]);
        }
    }

    // F = X^T @ weight   (K-dim 64)
    u64 facc[8][4];
#pragma unroll
    for (int rr = 0; rr < 8; rr++)
#pragma unroll
        for (int op = 0; op < 4; op++) facc[rr][op] = 0ull;

#pragma unroll 2
    for (int i = 0; i < NI; i++) {
        const float4 xa = *(const float4*)(sX + i*ROWS + row0);
        const float4 xb = *(const float4*)(sX + i*ROWS + row0 + 4);
        u64 xd[8];
        xd[0]=pack2(xa.x,xa.x); xd[1]=pack2(xa.y,xa.y); xd[2]=pack2(xa.z,xa.z); xd[3]=pack2(xa.w,xa.w);
        xd[4]=pack2(xb.x,xb.x); xd[5]=pack2(xb.y,xb.y); xd[6]=pack2(xb.z,xb.z); xd[7]=pack2(xb.w,xb.w);
        const u64* wp = (const u64*)(sW + i*NO + o0);
        u64 w0 = wp[0], w1 = wp[1], w2 = wp[2], w3 = wp[3];
#pragma unroll
        for (int rr = 0; rr < 8; rr++) {
            facc[rr][0] = fma2(xd[rr], w0, facc[rr][0]);
            facc[rr][1] = fma2(xd[rr], w1, facc[rr][1]);
            facc[rr][2] = fma2(xd[rr], w2, facc[rr][2]);
            facc[rr][3] = fma2(xd[rr], w3, facc[rr][3]);
        }
    }

    // ---- combine: out[n,o] = sum_k F*mat (k-reduction over rows), packed ----
    u64 part[4] = {0ull, 0ull, 0ull, 0ull};
#pragma unroll
    for (int rr = 0; rr < 8; rr++) {
#pragma unroll
        for (int op = 0; op < 4; op++)
            part[op] = fma2(facc[rr][op], macc[rr][op], part[op]);
    }

    const int my_nl = tr >> 1;   // rows row0..row0+7 all belong to n_local = tr/2
#pragma unroll
    for (int op = 0; op < 4; op++) {
        float2 v = unpack2(part[op]);
        atomicAdd(&sOut[my_nl*NO + o0 + 2*op + 0], v.x);
        atomicAdd(&sOut[my_nl*NO + o0 + 2*op + 1], v.y);
    }

    __syncthreads();

    // ---- epilogue: out layout (B, O, N), + bias ----
    for (int idx = tid; idx < TN*NO; idx += NTHREADS) {
        int o = idx >> 3, nl = idx & 7;
        out[((size_t)b*NO + o)*NN + n0 + nl] = sOut[nl*NO + o] + sBias[o];
    }

    // ---- second tuple element: support_points passthrough ----
    if (copy_sp) {
        for (int idx = blk*NTHREADS + tid; idx < SPN; idx += gridDim.x*NTHREADS)
            out[BON + idx] = support[idx];
    }
}

extern "C" void kernel_launch(void* const* d_in, const int* in_sizes, int n_in,
                              void* d_out, int out_size) {
    const float* input   = (const float*)d_in[0];
    const float* points  = (const float*)d_in[1];
    const float* support = (const float*)d_in[2];
    const float* weight  = (const float*)d_in[3];
    const float* bias    = (const float*)d_in[4];
    const float* W1      = (const float*)d_in[5];
    const float* b1      = (const float*)d_in[6];
    const float* W2      = (const float*)d_in[7];
    const float* b2      = (const float*)d_in[8];
    const float* W3      = (const float*)d_in[9];
    const float* b3      = (const float*)d_in[10];

    static int inited = 0;
    if (!inited) {
        cudaFuncSetAttribute(pccn_kernel,
                             cudaFuncAttributeMaxDynamicSharedMemorySize,
                             SMEM_BYTES);
        inited = 1;
    }
    int copy_sp = (out_size > BON) ? 1 : 0;
    pccn_kernel<<<NB*(NN/TN), NTHREADS, SMEM_BYTES>>>(
        input, points, support, weight, bias, W1, b1, W2, b2, W3, b3,
        (float*)d_out, copy_sp);
}